// round 9
// baseline (speedup 1.0000x reference)
#include <cuda_runtime.h>
#include <stdint.h>

// ---------------------------------------------------------------------------
// KMaxPool: per row of 4096 fp32, top-8 values in original index order.
// One warp per row, single pass. Warp-cooperative selection:
//   - warp top-8 kept DISTRIBUTED in lanes 0..7 (val desc), vmin = lane7 val
//   - 16-element batch max filter: 1 ballot per 16 elements (~1.25 slot/elem)
//   - batch hit (rare) -> __ldcv RELOAD of the 4 vectors (keeps them out of
//     the live range -> regs <= 32 -> 8 blocks/SM) -> quad -> exact inserts
//   - __launch_bounds__(256, 8) pins the 64-warp/SM occupancy (R8 lesson:
//     regs 37 cost 2 blocks/SM and more than the filter saved)
//   - epilogue: rank lanes 0..7 by original index, scatter-store 8 floats
// ---------------------------------------------------------------------------

#define FULLMASK 0xffffffffu

// Exact per-element processing (uniform ballot loop + distributed insert).
static __device__ __forceinline__ void proc(float v, uint32_t ubase,
                                            float& val, uint32_t& idx,
                                            float& vmin, bool lane0) {
    unsigned m = __ballot_sync(FULLMASK, v > vmin);
    while (m) {
        const int L = __ffs(m) - 1;
        m &= m - 1;
        const float    bv = __shfl_sync(FULLMASK, v, L);
        const uint32_t bi = ubase + ((uint32_t)L << 2);

        const float    pv = __shfl_up_sync(FULLMASK, val, 1);
        const uint32_t pi = __shfl_up_sync(FULLMASK, idx, 1);
        const bool keep = (val >= bv);            // incumbent wins ties
        const bool pk   = lane0 || (pv >= bv);    // lane0: conceptual prev=+inf
        val = keep ? val : (pk ? bv : pv);
        idx = keep ? idx : (pk ? bi : pi);

        vmin = __shfl_sync(FULLMASK, val, 7);
        if (!m) break;
        m &= __ballot_sync(FULLMASK, v > vmin);   // prune with tighter vmin
    }
}

// Quad: one ballot per 4 elements; exact path only on a hit.
static __device__ __forceinline__ void quad(uint4 q, uint32_t ubase,
                                            float& val, uint32_t& idx,
                                            float& vmin, bool lane0) {
    const float vx = __uint_as_float(q.x);
    const float vy = __uint_as_float(q.y);
    const float vz = __uint_as_float(q.z);
    const float vw = __uint_as_float(q.w);
    const float qm = fmaxf(fmaxf(vx, vy), fmaxf(vz, vw));
    if (__ballot_sync(FULLMASK, qm > vmin)) {
        proc(vx, ubase + 0, val, idx, vmin, lane0);
        proc(vy, ubase + 1, val, idx, vmin, lane0);
        proc(vz, ubase + 2, val, idx, vmin, lane0);
        proc(vw, ubase + 3, val, idx, vmin, lane0);
    }
}

static __device__ __forceinline__ float max4(uint4 q) {
    return fmaxf(fmaxf(__uint_as_float(q.x), __uint_as_float(q.y)),
                 fmaxf(__uint_as_float(q.z), __uint_as_float(q.w)));
}

__global__ void __launch_bounds__(256, 8) kmax8_kernel(const float* __restrict__ x,
                                                       float* __restrict__ out,
                                                       int nrows) {
    const int gw   = (int)((blockIdx.x * blockDim.x + threadIdx.x) >> 5);
    const int lane = threadIdx.x & 31;
    if (gw >= nrows) return;

    const uint4* row = reinterpret_cast<const uint4*>(x) + (size_t)gw * 1024;

    float    val  = __int_as_float(0xff800000);  // -inf (lanes 0..7 = top-8)
    uint32_t idx  = 0;
    float    vmin = __int_as_float(0xff800000);
    const bool lane0 = (lane == 0);

    // 8 batches x (4 float4 loads = 16 elements) per lane.
#pragma unroll 1
    for (int it = 0; it < 8; ++it) {
        const uint4* p = row + it * 128 + lane;
        // hot path: values die right after the max tree
        float ma, mb, mc, md;
        {
            uint4 a = p[0];
            uint4 b = p[32];
            uint4 c = p[64];
            uint4 d = p[96];
            ma = max4(a); mb = max4(b); mc = max4(c); md = max4(d);
        }
        const float bm = fmaxf(fmaxf(ma, mb), fmaxf(mc, md));

        if (__ballot_sync(FULLMASK, bm > vmin)) {
            // cold path: reload (L2-resident); __ldcv prevents CSE with the
            // hot-path loads so their registers stay dead across the branch
            const uint32_t u0 = (uint32_t)(it * 512);
            uint4 ra = __ldcv(p);
            quad(ra, u0 + 0,   val, idx, vmin, lane0);
            uint4 rb = __ldcv(p + 32);
            quad(rb, u0 + 128, val, idx, vmin, lane0);
            uint4 rc = __ldcv(p + 64);
            quad(rc, u0 + 256, val, idx, vmin, lane0);
            uint4 rd = __ldcv(p + 96);
            quad(rd, u0 + 384, val, idx, vmin, lane0);
        }
    }

    // Epilogue: lanes 0..7 hold the top-8 (val desc, unique idx).
    // rank = number of held indices smaller than mine -> output position.
    int rank = 0;
#pragma unroll
    for (int dd = 1; dd < 8; ++dd) {
        uint32_t oi = __shfl_sync(FULLMASK, idx, (lane + dd) & 7);
        rank += (oi < idx) ? 1 : 0;
    }
    if (lane < 8) out[(size_t)gw * 8 + rank] = val;
}

extern "C" void kernel_launch(void* const* d_in, const int* in_sizes, int n_in,
                              void* d_out, int out_size) {
    const float* x = (const float*)d_in[0];
    float* out = (float*)d_out;
    int nrows = in_sizes[0] / 4096;
    const int threads = 256;
    const int warps_per_block = threads / 32;
    int blocks = (nrows + warps_per_block - 1) / warps_per_block;
    kmax8_kernel<<<blocks, threads>>>(x, out, nrows);
}

// round 10
// speedup vs baseline: 1.2050x; 1.2050x over previous
#include <cuda_runtime.h>
#include <stdint.h>

// ---------------------------------------------------------------------------
// KMaxPool: per row of 4096 fp32, top-8 values in original index order.
// One warp per row, single pass. Warp-cooperative selection.
//   - warp top-8 kept DISTRIBUTED in lanes 0..7 (val desc), vmin = lane7 val
//   - R6 load structure (4 x LDG.128 upfront, regs ~32, 8 blocks/SM) --
//     proven fastest memory behavior; occupancy is the memory pipeline here
//   - ONE change vs R6: each quad gated by a single ballot (3 FMNMX + setp +
//     vote) instead of 4 per-element ballots -> ~1.8 alu slots/elem vs 3
//   - quad ballot j depends only on load j: loads b,c,d overlap quad(a) work
//     (R9 lesson: a batch-of-16 ballot serializes on the last load)
//   - exact path (per-element ballot + distributed shfl insert) unchanged
//   - epilogue: rank lanes 0..7 by original index, scatter-store 8 floats
// ---------------------------------------------------------------------------

#define FULLMASK 0xffffffffu

// Exact per-element processing (uniform ballot loop + distributed insert).
static __device__ __forceinline__ void proc(float v, uint32_t ubase,
                                            float& val, uint32_t& idx,
                                            float& vmin, bool lane0) {
    unsigned m = __ballot_sync(FULLMASK, v > vmin);
    while (m) {
        const int L = __ffs(m) - 1;
        m &= m - 1;
        const float    bv = __shfl_sync(FULLMASK, v, L);
        const uint32_t bi = ubase + ((uint32_t)L << 2);

        const float    pv = __shfl_up_sync(FULLMASK, val, 1);
        const uint32_t pi = __shfl_up_sync(FULLMASK, idx, 1);
        const bool keep = (val >= bv);            // incumbent wins ties
        const bool pk   = lane0 || (pv >= bv);    // lane0: conceptual prev=+inf
        val = keep ? val : (pk ? bv : pv);
        idx = keep ? idx : (pk ? bi : pi);

        vmin = __shfl_sync(FULLMASK, val, 7);
        if (!m) break;
        m &= __ballot_sync(FULLMASK, v > vmin);   // prune with tighter vmin
    }
}

// Quad: one ballot per 4 elements; exact path only on a hit.
static __device__ __forceinline__ void quad(uint4 q, uint32_t ubase,
                                            float& val, uint32_t& idx,
                                            float& vmin, bool lane0) {
    const float vx = __uint_as_float(q.x);
    const float vy = __uint_as_float(q.y);
    const float vz = __uint_as_float(q.z);
    const float vw = __uint_as_float(q.w);
    const float qm = fmaxf(fmaxf(vx, vy), fmaxf(vz, vw));
    if (__ballot_sync(FULLMASK, qm > vmin)) {
        proc(vx, ubase + 0, val, idx, vmin, lane0);
        proc(vy, ubase + 1, val, idx, vmin, lane0);
        proc(vz, ubase + 2, val, idx, vmin, lane0);
        proc(vw, ubase + 3, val, idx, vmin, lane0);
    }
}

__global__ void __launch_bounds__(256) kmax8_kernel(const float* __restrict__ x,
                                                    float* __restrict__ out,
                                                    int nrows) {
    const int gw   = (int)((blockIdx.x * blockDim.x + threadIdx.x) >> 5);
    const int lane = threadIdx.x & 31;
    if (gw >= nrows) return;

    const uint4* row = reinterpret_cast<const uint4*>(x) + (size_t)gw * 1024;

    float    val  = __int_as_float(0xff800000);  // -inf (lanes 0..7 = top-8)
    uint32_t idx  = 0;
    float    vmin = __int_as_float(0xff800000);
    const bool lane0 = (lane == 0);

    // 8 batches x (4 float4 loads = 16 elements) per lane, R6 structure.
#pragma unroll 1
    for (int it = 0; it < 8; ++it) {
        const int p0 = it * 128 + lane;
        uint4 a = row[p0];
        uint4 b = row[p0 + 32];
        uint4 c = row[p0 + 64];
        uint4 d = row[p0 + 96];

        const uint32_t u0 = (uint32_t)(it * 512);
        quad(a, u0 + 0,   val, idx, vmin, lane0);
        quad(b, u0 + 128, val, idx, vmin, lane0);
        quad(c, u0 + 256, val, idx, vmin, lane0);
        quad(d, u0 + 384, val, idx, vmin, lane0);
    }

    // Epilogue: lanes 0..7 hold the top-8 (val desc, unique idx).
    // rank = number of held indices smaller than mine -> output position.
    int rank = 0;
#pragma unroll
    for (int dd = 1; dd < 8; ++dd) {
        uint32_t oi = __shfl_sync(FULLMASK, idx, (lane + dd) & 7);
        rank += (oi < idx) ? 1 : 0;
    }
    if (lane < 8) out[(size_t)gw * 8 + rank] = val;
}

extern "C" void kernel_launch(void* const* d_in, const int* in_sizes, int n_in,
                              void* d_out, int out_size) {
    const float* x = (const float*)d_in[0];
    float* out = (float*)d_out;
    int nrows = in_sizes[0] / 4096;
    const int threads = 256;
    const int warps_per_block = threads / 32;
    int blocks = (nrows + warps_per_block - 1) / warps_per_block;
    kmax8_kernel<<<blocks, threads>>>(x, out, nrows);
}